// round 14
// baseline (speedup 1.0000x reference)
#include <cuda_runtime.h>

typedef unsigned long long ULL;

// ---------------- problem sizes ----------------
#define BQ   16384
#define TQ   96
#define FQ   16
#define HQ   64
#define HORQ 24
#define OUTQ 16

// ---------------- global weight scratch layout (floats) ----------------
// LSTM matrices are stored DUPLICATED: row k has 512 floats = 256 gate-pairs,
// pair p = (w[k][p], w[k][p]) so the GEMM loads pre-splatted f32x2 operands.
#define OFF_EIH0 0          // 16 x 512
#define OFF_EHH0 8192       // 64 x 512 each
#define OFF_EIH1 40960
#define OFF_EHH1 73728
#define OFF_DIH0 106496
#define OFF_DHH0 139264
#define OFF_DIH1 172032
#define OFF_DHH1 204800
#define OFF_W1D  237568     // 64 x 128 (64 units duplicated)
#define OFF_W2T  245760     // 64 x 16
#define OFF_BE0  246784     // 256 each (permuted, not duplicated)
#define OFF_BE1  247040
#define OFF_BD0  247296
#define OFF_BD1  247552
#define OFF_B1   247808     // 64
#define OFF_B2   247872     // 16
#define WBUF_TOTAL 247888

__device__ __align__(16) float g_wbuf[WBUF_TOTAL];

// ---------------- shared memory layout (floats) ----------------
// x double-buffer (2 x 16 x 132) | h0 (64x132) | h1 (64x132) | y1 (64x132)
// | c ([32][512])
#define XS_OFF   0
#define H0_OFF   4224
#define H1_OFF   (H0_OFF + 8448)
#define Y1_OFF   (H1_OFF + 8448)
#define CS_OFF   (Y1_OFF + 8448)
#define SMEM_FLOATS (CS_OFF + 32*512)
#define SMEM_BYTES  (SMEM_FLOATS * 4)

// h row stride: 132 floats = 66 ULLs = 33 ulonglong2
#define HROW_U2  33

// ---------------- f32x2 helpers ----------------
__device__ __forceinline__ ULL pack2(float lo, float hi) {
    ULL r;
    asm("mov.b64 %0, {%1, %2};" : "=l"(r) : "f"(lo), "f"(hi));
    return r;
}
__device__ __forceinline__ float2 unpack2(ULL v) {
    float2 r;
    asm("mov.b64 {%0, %1}, %2;" : "=f"(r.x), "=f"(r.y) : "l"(v));
    return r;
}
__device__ __forceinline__ ULL splat2(float x) { return pack2(x, x); }
__device__ __forceinline__ void ffma2(ULL& d, ULL a, ULL b) {
    asm("fma.rn.f32x2 %0, %1, %2, %0;" : "+l"(d) : "l"(a), "l"(b));
}

// fast activations (MUFU-based) — proven 2.9e-8 end-to-end
__device__ __forceinline__ float sigm_(float x) {
    return __fdividef(1.f, 1.f + __expf(-x));
}
__device__ __forceinline__ float tanh_(float x) {
    return __fdividef(2.f, 1.f + __expf(-2.f * x)) - 1.f;
}

// ---------------- single merged prep kernel ----------------
// grid (128, 8) x 256. m = blockIdx.y:
// m 0..6: the seven 64x256 LSTM matrices -> duplicated 64x512 layout.
// m == 7: EIH0 (16x256 -> 16x512 dup), W1D (dup), W2T, biases, b1, b2.
__global__ void prep_all(const float* __restrict__ eih0, const float* __restrict__ ehh0,
                         const float* __restrict__ eb0,
                         const float* __restrict__ eih1, const float* __restrict__ ehh1,
                         const float* __restrict__ eb1,
                         const float* __restrict__ dih0, const float* __restrict__ dhh0,
                         const float* __restrict__ db0,
                         const float* __restrict__ dih1, const float* __restrict__ dhh1,
                         const float* __restrict__ db1,
                         const float* __restrict__ W1, const float* __restrict__ b1,
                         const float* __restrict__ W2, const float* __restrict__ b2)
{
    int m = blockIdx.y;
    int i = blockIdx.x * 256 + threadIdx.x;   // 0..32767

    if (m < 7) {
        const float* src;
        int off;
        switch (m) {
            case 0: src = ehh0; off = OFF_EHH0; break;
            case 1: src = eih1; off = OFF_EIH1; break;
            case 2: src = ehh1; off = OFF_EHH1; break;
            case 3: src = dih0; off = OFF_DIH0; break;
            case 4: src = dhh0; off = OFF_DHH0; break;
            case 5: src = dih1; off = OFF_DIH1; break;
            default: src = dhh1; off = OFF_DHH1; break;
        }
        int k = i >> 9, q = i & 511;
        int p = q >> 1;                 // permuted gate idx (duplicated)
        int u = p >> 2, tt = p & 3;
        g_wbuf[off + i] = src[(tt * 64 + u) * 64 + k];
        return;
    }

    if (i < 8192) {                              // EIH0 dup, K=16
        int k = i >> 9, q = i & 511;
        int p = q >> 1;
        int u = p >> 2, tt = p & 3;
        g_wbuf[OFF_EIH0 + i] = eih0[(tt * 64 + u) * 16 + k];
    } else if (i < 16384) {                      // W1D dup: [k][2u..2u+1] = W1[u][k]
        int j = i - 8192;
        int k = j >> 7, q = j & 127;
        int u = q >> 1;
        g_wbuf[OFF_W1D + j] = W1[u * 64 + k];
    } else if (i < 17408) {                      // W2T
        int j = i - 16384;
        int o = j >> 6, k = j & 63;
        g_wbuf[OFF_W2T + k * 16 + o] = W2[j];
    } else if (i < 18432) {                      // 4 LSTM biases, permuted
        int j = i - 17408;
        int which = j >> 8;
        int p = j & 255;
        int u = p >> 2, tt = p & 3;
        const float* src = (which == 0) ? eb0 : (which == 1) ? eb1
                         : (which == 2) ? db0 : db1;
        int off = (which == 0) ? OFF_BE0 : (which == 1) ? OFF_BE1
                : (which == 2) ? OFF_BD0 : OFF_BD1;
        g_wbuf[off + p] = src[tt * 64 + u];
    } else if (i < 18496) {
        g_wbuf[OFF_B1 + (i - 18432)] = b1[i - 18432];
    } else if (i < 18512) {
        g_wbuf[OFF_B2 + (i - 18496)] = b2[i - 18496];
    }
}

// ---------------- main fused kernel ----------------
// 512 threads, eg-fast mapping: gg = tid>>4 (0..31), eg = tid&15 (0..15).
// Thread tile: gates g0=gg*8 (units u0=gg*2,u0+1) x elems e0=eg*8 (4 pairs).
// acc[g*4+ep]: g = local gate 0..7 (unit ui=g>>2, type g&3), ep = elem pair.

__device__ __forceinline__ void init_acc(ULL* acc, const float* __restrict__ bseg, int g0)
{
#pragma unroll
    for (int g = 0; g < 8; g++) {
        ULL bp = splat2(bseg[g0 + g]);
#pragma unroll
        for (int ep = 0; ep < 4; ep++) acc[g * 4 + ep] = bp;
    }
}

template <int K>
__device__ __forceinline__ void gemm_acc(ULL* acc, const float* __restrict__ Wd,
                                         const float* __restrict__ src, int g0, int e0)
{
    // Wd row = 512 floats = 256 ULLs = 128 ulonglong2 (pre-duplicated gate pairs)
    const ulonglong2* wp = (const ulonglong2*)Wd + (g0 >> 1);
    const ulonglong2* hp = (const ulonglong2*)(src + e0);   // row stride HROW_U2
    ulonglong2 w0 = wp[0], w1 = wp[1], w2 = wp[2], w3 = wp[3];
    ulonglong2 hA = hp[0], hB = hp[1];
#pragma unroll 2
    for (int k = 0; k < K; k++) {
        ULL wc[8];
        wc[0] = w0.x; wc[1] = w0.y; wc[2] = w1.x; wc[3] = w1.y;
        wc[4] = w2.x; wc[5] = w2.y; wc[6] = w3.x; wc[7] = w3.y;
        ULL hc[4];
        hc[0] = hA.x; hc[1] = hA.y; hc[2] = hB.x; hc[3] = hB.y;
        if (k + 1 < K) {                // prefetch next k
            wp += 128;                  // 128 ulonglong2 per weight row
            hp += HROW_U2;              // 33 ulonglong2 per h row
            w0 = wp[0]; w1 = wp[1]; w2 = wp[2]; w3 = wp[3];
            hA = hp[0]; hB = hp[1];
        }
#pragma unroll
        for (int g = 0; g < 8; g++)
#pragma unroll
            for (int ep = 0; ep < 4; ep++)
                ffma2(acc[g * 4 + ep], wc[g], hc[ep]);
    }
}

// gate activation + state update; c in SMEM layout [slot][512] (conflict-free)
__device__ __forceinline__ void lstm_act(const ULL* acc, float* __restrict__ cbase,
                                         float* __restrict__ h_s, int u0, int e0, int tid)
{
#pragma unroll
    for (int ui = 0; ui < 2; ui++) {
        float hv[8];
#pragma unroll
        for (int ep = 0; ep < 4; ep++) {
            float2 iv = unpack2(acc[(ui * 4 + 0) * 4 + ep]);
            float2 fv = unpack2(acc[(ui * 4 + 1) * 4 + ep]);
            float2 gv = unpack2(acc[(ui * 4 + 2) * 4 + ep]);
            float2 ov = unpack2(acc[(ui * 4 + 3) * 4 + ep]);
            float* cp0 = cbase + (ui * 8 + ep * 2 + 0) * 512 + tid;
            float* cp1 = cbase + (ui * 8 + ep * 2 + 1) * 512 + tid;
            float c0 = *cp0, c1 = *cp1;
            float cn0 = sigm_(fv.x) * c0 + sigm_(iv.x) * tanh_(gv.x);
            float cn1 = sigm_(fv.y) * c1 + sigm_(iv.y) * tanh_(gv.y);
            *cp0 = cn0; *cp1 = cn1;
            hv[ep * 2 + 0] = sigm_(ov.x) * tanh_(cn0);
            hv[ep * 2 + 1] = sigm_(ov.y) * tanh_(cn1);
        }
        float4* dst = (float4*)(h_s + (u0 + ui) * 132 + e0);
        dst[0] = make_float4(hv[0], hv[1], hv[2], hv[3]);
        dst[1] = make_float4(hv[4], hv[5], hv[6], hv[7]);
    }
}

__global__ void __launch_bounds__(512, 1)
seq2seq_main(const float* __restrict__ X, const float* __restrict__ biasB,
             float* __restrict__ out)
{
    extern __shared__ float sm[];
    float* xs   = sm + XS_OFF;      // two buffers of 2112 floats
    float* h0_s = sm + H0_OFF;
    float* h1_s = sm + H1_OFF;
    float* y1_s = sm + Y1_OFF;
    float* c_s  = sm + CS_OFF;
    const float* gb = g_wbuf;

    const int tid = threadIdx.x;
    const int gg  = tid >> 4;     // 0..31
    const int eg  = tid & 15;     // 0..15
    const int g0  = gg * 8;
    const int e0  = eg * 8;
    const int u0  = gg * 2;
    const int b0  = blockIdx.x * 128;

    float* c0base = c_s;              // layer 0: slots 0..15
    float* c1base = c_s + 16 * 512;   // layer 1: slots 16..31

    // zero h0, h1, c
    for (int i = H0_OFF + tid; i < H1_OFF + 8448; i += 512) sm[i] = 0.f;
    for (int i = CS_OFF + tid; i < SMEM_FLOATS; i += 512) sm[i] = 0.f;

    // x staging mapping + preload x(0) into buffer 0
    const int xe = tid >> 2;            // elem 0..127
    const int xf = (tid & 3) * 4;       // feature 0,4,8,12
    const float* xbase = X + (size_t)(b0 + xe) * (TQ * FQ) + xf;
    {
        float4 v = *(const float4*)(xbase);
        xs[(xf + 0) * 132 + xe] = v.x;
        xs[(xf + 1) * 132 + xe] = v.y;
        xs[(xf + 2) * 132 + xe] = v.z;
        xs[(xf + 3) * 132 + xe] = v.w;
    }
    __syncthreads();

    ULL acc[32];

    // ================= encoder (3 barriers/step) =================
    for (int t = 0; t < TQ; t++) {
        // issue LDG for x(t+1) early (clamped; latency hidden under gemm0)
        int tn = (t + 1 < TQ) ? t + 1 : TQ - 1;
        float4 xv = *(const float4*)(xbase + tn * FQ);

        init_acc(acc, gb + OFF_BE0, g0);
        gemm_acc<16>(acc, gb + OFF_EIH0, xs + (t & 1) * 2112, g0, e0);
        gemm_acc<64>(acc, gb + OFF_EHH0, h0_s, g0, e0);
        __syncthreads();                            // S2: gemm0 reads done
        lstm_act(acc, c0base, h0_s, u0, e0, tid);   // writes h0
        {   // stage x(t+1) into the other buffer (its old readers long done)
            float* xb = xs + ((t + 1) & 1) * 2112;
            xb[(xf + 0) * 132 + xe] = xv.x;
            xb[(xf + 1) * 132 + xe] = xv.y;
            xb[(xf + 2) * 132 + xe] = xv.z;
            xb[(xf + 3) * 132 + xe] = xv.w;
        }
        __syncthreads();                            // S3: h0 + x(t+1) visible
        init_acc(acc, gb + OFF_BE1, g0);
        gemm_acc<64>(acc, gb + OFF_EIH1, h0_s, g0, e0);
        gemm_acc<64>(acc, gb + OFF_EHH1, h1_s, g0, e0);
        __syncthreads();                            // S4: gemm1 reads done
        lstm_act(acc, c1base, h1_s, u0, e0, tid);   // writes h1
        // next-iter S2 orders h1 writes before gemm1(t+1); gemm0(t+1) doesn't read h1
    }
    __syncthreads();    // encoder-final h0/h1 visible to decoder

    // ================= decoder (5 barriers/step) =================
    // carry: dh0 = enc h0 (h0_s), dh1 = enc h1 (h1_s); c := 0 (thread-owned slots)
#pragma unroll
    for (int j = 0; j < 16; j++) {
        c0base[j * 512 + tid] = 0.f;
        c1base[j * 512 + tid] = 0.f;
    }

    // head gemm2 mapping + per-batch bias preload
    const int o2  = tid & 15;
    const int e0b = (tid >> 4) * 4;
    float bb[4];
#pragma unroll
    for (int j = 0; j < 4; j++)
        bb[j] = biasB[(size_t)(b0 + e0b + j) * OUTQ + o2];
    const float b2v = gb[OFF_B2 + o2];

    for (int s = 0; s < HORQ; s++) {
        init_acc(acc, gb + OFF_BD0, g0);
        gemm_acc<64>(acc, gb + OFF_DIH0, h1_s, g0, e0);
        gemm_acc<64>(acc, gb + OFF_DHH0, h0_s, g0, e0);
        __syncthreads();                            // S2d
        lstm_act(acc, c0base, h0_s, u0, e0, tid);   // h0 := new dh0
        __syncthreads();                            // S3d
        init_acc(acc, gb + OFF_BD1, g0);
        gemm_acc<64>(acc, gb + OFF_DIH1, h0_s, g0, e0);
        gemm_acc<64>(acc, gb + OFF_DHH1, h1_s, g0, e0);
        __syncthreads();                            // S4d
        lstm_act(acc, c1base, h1_s, u0, e0, tid);   // h1 := new dh1
        __syncthreads();                            // S5d

        // head gemm1: y1 = relu(dh1 @ W1^T + b1); thread = 2 units x 4 elem-pairs
        {
            ULL a2[8];
            ULL bp0 = splat2(gb[OFF_B1 + u0]);
            ULL bp1 = splat2(gb[OFF_B1 + u0 + 1]);
#pragma unroll
            for (int ep = 0; ep < 4; ep++) { a2[ep] = bp0; a2[4 + ep] = bp1; }
            const ulonglong2* wp = (const ulonglong2*)(gb + OFF_W1D) + gg; // row stride 32
            const ulonglong2* hp = (const ulonglong2*)(h1_s + e0);         // row stride 33
#pragma unroll 4
            for (int k = 0; k < 64; k++) {
                ulonglong2 w = wp[k * 32];           // (u0 dup, u0+1 dup)
                ulonglong2 hA = hp[k * HROW_U2];
                ulonglong2 hB = hp[k * HROW_U2 + 1];
                ffma2(a2[0], w.x, hA.x);
                ffma2(a2[1], w.x, hA.y);
                ffma2(a2[2], w.x, hB.x);
                ffma2(a2[3], w.x, hB.y);
                ffma2(a2[4], w.y, hA.x);
                ffma2(a2[5], w.y, hA.y);
                ffma2(a2[6], w.y, hB.x);
                ffma2(a2[7], w.y, hB.y);
            }
            float r0[8], r1[8];
#pragma unroll
            for (int ep = 0; ep < 4; ep++) {
                float2 v0 = unpack2(a2[ep]);
                float2 v1 = unpack2(a2[4 + ep]);
                r0[ep * 2 + 0] = fmaxf(v0.x, 0.f);
                r0[ep * 2 + 1] = fmaxf(v0.y, 0.f);
                r1[ep * 2 + 0] = fmaxf(v1.x, 0.f);
                r1[ep * 2 + 1] = fmaxf(v1.y, 0.f);
            }
            float4* d0 = (float4*)(y1_s + (u0 + 0) * 132 + e0);
            float4* d1 = (float4*)(y1_s + (u0 + 1) * 132 + e0);
            d0[0] = make_float4(r0[0], r0[1], r0[2], r0[3]);
            d0[1] = make_float4(r0[4], r0[5], r0[6], r0[7]);
            d1[0] = make_float4(r1[0], r1[1], r1[2], r1[3]);
            d1[1] = make_float4(r1[4], r1[5], r1[6], r1[7]);
        }
        __syncthreads();                            // S6d: y1 visible

        // head gemm2: y = y1 @ W2^T + b2 + last_bias
        {
            float a3[4] = { b2v, b2v, b2v, b2v };
            const float* wp2 = gb + OFF_W2T + o2;  // row stride 16
            const float* yp  = y1_s + e0b;
#pragma unroll 4
            for (int k = 0; k < 64; k++) {
                float w = wp2[k * 16];
                float4 yv = *(const float4*)(yp + k * 132);
                a3[0] = fmaf(w, yv.x, a3[0]);
                a3[1] = fmaf(w, yv.y, a3[1]);
                a3[2] = fmaf(w, yv.z, a3[2]);
                a3[3] = fmaf(w, yv.w, a3[3]);
            }
#pragma unroll
            for (int j = 0; j < 4; j++)
                out[(size_t)(b0 + e0b + j) * (HORQ * OUTQ) + s * OUTQ + o2] = a3[j] + bb[j];
        }
        // no end barrier: next-step S2d..S5d separate all conflicting accesses
    }
}

// ---------------- launch ----------------
extern "C" void kernel_launch(void* const* d_in, const int* in_sizes, int n_in,
                              void* d_out, int out_size)
{
    (void)in_sizes; (void)n_in; (void)out_size;
    const float* X    = (const float*)d_in[0];
    const float* bias = (const float*)d_in[1];
    // d_in[2] = X_mask (all true, unused by reference)
    const float* eih0 = (const float*)d_in[3];
    const float* ehh0 = (const float*)d_in[4];
    const float* eb0  = (const float*)d_in[5];
    const float* eih1 = (const float*)d_in[6];
    const float* ehh1 = (const float*)d_in[7];
    const float* eb1  = (const float*)d_in[8];
    const float* dih0 = (const float*)d_in[9];
    const float* dhh0 = (const float*)d_in[10];
    const float* db0  = (const float*)d_in[11];
    const float* dih1 = (const float*)d_in[12];
    const float* dhh1 = (const float*)d_in[13];
    const float* db1  = (const float*)d_in[14];
    const float* rW1  = (const float*)d_in[15];
    const float* rb1  = (const float*)d_in[16];
    const float* rW2  = (const float*)d_in[17];
    const float* rb2  = (const float*)d_in[18];
    float* out = (float*)d_out;

    prep_all<<<dim3(128, 8), 256>>>(eih0, ehh0, eb0, eih1, ehh1, eb1,
                                    dih0, dhh0, db0, dih1, dhh1, db1,
                                    rW1, rb1, rW2, rb2);

    cudaFuncSetAttribute(seq2seq_main,
                         cudaFuncAttributeMaxDynamicSharedMemorySize, SMEM_BYTES);
    seq2seq_main<<<128, 512, SMEM_BYTES>>>(X, bias, out);
}

// round 15
// speedup vs baseline: 1.0047x; 1.0047x over previous
#include <cuda_runtime.h>

typedef unsigned long long ULL;

// ---------------- problem sizes ----------------
#define BQ   16384
#define TQ   96
#define FQ   16
#define HQ   64
#define HORQ 24
#define OUTQ 16

// ---------------- global weight scratch layout (floats) ----------------
// LSTM matrices are stored DUPLICATED: row k has 512 floats = 256 gate-pairs,
// pair p = (w[k][p], w[k][p]) so the GEMM loads pre-splatted f32x2 operands.
#define OFF_EIH0 0          // 16 x 512
#define OFF_EHH0 8192       // 64 x 512 each
#define OFF_EIH1 40960
#define OFF_EHH1 73728
#define OFF_DIH0 106496
#define OFF_DHH0 139264
#define OFF_DIH1 172032
#define OFF_DHH1 204800
#define OFF_W1D  237568     // 64 x 128 (64 units duplicated)
#define OFF_W2T  245760     // 64 x 16
#define OFF_BE0  246784     // 256 each (permuted, not duplicated)
#define OFF_BE1  247040
#define OFF_BD0  247296
#define OFF_BD1  247552
#define OFF_B1   247808     // 64
#define OFF_B2   247872     // 16
#define WBUF_TOTAL 247888

__device__ __align__(16) float g_wbuf[WBUF_TOTAL];

// ---------------- shared memory layout (floats) ----------------
// x double-buffer (2 x 16 x 132) | h0 (64x132) | h1 (64x132) | y1 (64x132)
// | c ([32][512])
#define XS_OFF   0
#define H0_OFF   4224
#define H1_OFF   (H0_OFF + 8448)
#define Y1_OFF   (H1_OFF + 8448)
#define CS_OFF   (Y1_OFF + 8448)
#define SMEM_FLOATS (CS_OFF + 32*512)
#define SMEM_BYTES  (SMEM_FLOATS * 4)

// h row stride: 132 floats = 66 ULLs = 33 ulonglong2
#define HROW_U2  33

// ---------------- f32x2 helpers ----------------
__device__ __forceinline__ ULL pack2(float lo, float hi) {
    ULL r;
    asm("mov.b64 %0, {%1, %2};" : "=l"(r) : "f"(lo), "f"(hi));
    return r;
}
__device__ __forceinline__ float2 unpack2(ULL v) {
    float2 r;
    asm("mov.b64 {%0, %1}, %2;" : "=f"(r.x), "=f"(r.y) : "l"(v));
    return r;
}
__device__ __forceinline__ ULL splat2(float x) { return pack2(x, x); }
__device__ __forceinline__ void ffma2(ULL& d, ULL a, ULL b) {
    asm("fma.rn.f32x2 %0, %1, %2, %0;" : "+l"(d) : "l"(a), "l"(b));
}

// fast activations (MUFU-based) — proven 2.9e-8 end-to-end
__device__ __forceinline__ float sigm_(float x) {
    return __fdividef(1.f, 1.f + __expf(-x));
}
__device__ __forceinline__ float tanh_(float x) {
    return __fdividef(2.f, 1.f + __expf(-2.f * x)) - 1.f;
}

// ---------------- single merged prep kernel ----------------
// grid (128, 8) x 256. m = blockIdx.y:
// m 0..6: the seven 64x256 LSTM matrices -> duplicated 64x512 layout.
// m == 7: EIH0 (16x256 -> 16x512 dup), W1D (dup), W2T, biases, b1, b2.
__global__ void prep_all(const float* __restrict__ eih0, const float* __restrict__ ehh0,
                         const float* __restrict__ eb0,
                         const float* __restrict__ eih1, const float* __restrict__ ehh1,
                         const float* __restrict__ eb1,
                         const float* __restrict__ dih0, const float* __restrict__ dhh0,
                         const float* __restrict__ db0,
                         const float* __restrict__ dih1, const float* __restrict__ dhh1,
                         const float* __restrict__ db1,
                         const float* __restrict__ W1, const float* __restrict__ b1,
                         const float* __restrict__ W2, const float* __restrict__ b2)
{
    int m = blockIdx.y;
    int i = blockIdx.x * 256 + threadIdx.x;   // 0..32767

    if (m < 7) {
        const float* src;
        int off;
        switch (m) {
            case 0: src = ehh0; off = OFF_EHH0; break;
            case 1: src = eih1; off = OFF_EIH1; break;
            case 2: src = ehh1; off = OFF_EHH1; break;
            case 3: src = dih0; off = OFF_DIH0; break;
            case 4: src = dhh0; off = OFF_DHH0; break;
            case 5: src = dih1; off = OFF_DIH1; break;
            default: src = dhh1; off = OFF_DHH1; break;
        }
        int k = i >> 9, q = i & 511;
        int p = q >> 1;                 // permuted gate idx (duplicated)
        int u = p >> 2, tt = p & 3;
        g_wbuf[off + i] = src[(tt * 64 + u) * 64 + k];
        return;
    }

    if (i < 8192) {                              // EIH0 dup, K=16
        int k = i >> 9, q = i & 511;
        int p = q >> 1;
        int u = p >> 2, tt = p & 3;
        g_wbuf[OFF_EIH0 + i] = eih0[(tt * 64 + u) * 16 + k];
    } else if (i < 16384) {                      // W1D dup: [k][2u..2u+1] = W1[u][k]
        int j = i - 8192;
        int k = j >> 7, q = j & 127;
        int u = q >> 1;
        g_wbuf[OFF_W1D + j] = W1[u * 64 + k];
    } else if (i < 17408) {                      // W2T
        int j = i - 16384;
        int o = j >> 6, k = j & 63;
        g_wbuf[OFF_W2T + k * 16 + o] = W2[j];
    } else if (i < 18432) {                      // 4 LSTM biases, permuted
        int j = i - 17408;
        int which = j >> 8;
        int p = j & 255;
        int u = p >> 2, tt = p & 3;
        const float* src = (which == 0) ? eb0 : (which == 1) ? eb1
                         : (which == 2) ? db0 : db1;
        int off = (which == 0) ? OFF_BE0 : (which == 1) ? OFF_BE1
                : (which == 2) ? OFF_BD0 : OFF_BD1;
        g_wbuf[off + p] = src[tt * 64 + u];
    } else if (i < 18496) {
        g_wbuf[OFF_B1 + (i - 18432)] = b1[i - 18432];
    } else if (i < 18512) {
        g_wbuf[OFF_B2 + (i - 18496)] = b2[i - 18496];
    }
}

// ---------------- main fused kernel ----------------
// 512 threads, eg-fast mapping: gg = tid>>4 (0..31), eg = tid&15 (0..15).
// Thread tile: gates g0=gg*8 (units u0=gg*2,u0+1) x elems e0=eg*8 (4 pairs).
// acc[g*4+ep]: g = local gate 0..7 (unit ui=g>>2, type g&3), ep = elem pair.

__device__ __forceinline__ void init_acc(ULL* acc, const float* __restrict__ bseg, int g0)
{
#pragma unroll
    for (int g = 0; g < 8; g++) {
        ULL bp = splat2(bseg[g0 + g]);
#pragma unroll
        for (int ep = 0; ep < 4; ep++) acc[g * 4 + ep] = bp;
    }
}

template <int K>
__device__ __forceinline__ void gemm_acc(ULL* acc, const float* __restrict__ Wd,
                                         const float* __restrict__ src, int g0, int e0)
{
    // Wd row = 512 floats = 256 ULLs = 128 ulonglong2 (pre-duplicated gate pairs)
    const ulonglong2* wp = (const ulonglong2*)Wd + (g0 >> 1);
    const ulonglong2* hp = (const ulonglong2*)(src + e0);   // row stride HROW_U2
    ulonglong2 w0 = wp[0], w1 = wp[1], w2 = wp[2], w3 = wp[3];
    ulonglong2 hA = hp[0], hB = hp[1];
#pragma unroll 2
    for (int k = 0; k < K; k++) {
        ULL wc[8];
        wc[0] = w0.x; wc[1] = w0.y; wc[2] = w1.x; wc[3] = w1.y;
        wc[4] = w2.x; wc[5] = w2.y; wc[6] = w3.x; wc[7] = w3.y;
        ULL hc[4];
        hc[0] = hA.x; hc[1] = hA.y; hc[2] = hB.x; hc[3] = hB.y;
        if (k + 1 < K) {                // prefetch next k
            wp += 128;                  // 128 ulonglong2 per weight row
            hp += HROW_U2;              // 33 ulonglong2 per h row
            w0 = wp[0]; w1 = wp[1]; w2 = wp[2]; w3 = wp[3];
            hA = hp[0]; hB = hp[1];
        }
#pragma unroll
        for (int g = 0; g < 8; g++)
#pragma unroll
            for (int ep = 0; ep < 4; ep++)
                ffma2(acc[g * 4 + ep], wc[g], hc[ep]);
    }
}

// gate activation + state update; c in SMEM layout [slot][512] (conflict-free)
__device__ __forceinline__ void lstm_act(const ULL* acc, float* __restrict__ cbase,
                                         float* __restrict__ h_s, int u0, int e0, int tid)
{
#pragma unroll
    for (int ui = 0; ui < 2; ui++) {
        float hv[8];
#pragma unroll
        for (int ep = 0; ep < 4; ep++) {
            float2 iv = unpack2(acc[(ui * 4 + 0) * 4 + ep]);
            float2 fv = unpack2(acc[(ui * 4 + 1) * 4 + ep]);
            float2 gv = unpack2(acc[(ui * 4 + 2) * 4 + ep]);
            float2 ov = unpack2(acc[(ui * 4 + 3) * 4 + ep]);
            float* cp0 = cbase + (ui * 8 + ep * 2 + 0) * 512 + tid;
            float* cp1 = cbase + (ui * 8 + ep * 2 + 1) * 512 + tid;
            float c0 = *cp0, c1 = *cp1;
            float cn0 = sigm_(fv.x) * c0 + sigm_(iv.x) * tanh_(gv.x);
            float cn1 = sigm_(fv.y) * c1 + sigm_(iv.y) * tanh_(gv.y);
            *cp0 = cn0; *cp1 = cn1;
            hv[ep * 2 + 0] = sigm_(ov.x) * tanh_(cn0);
            hv[ep * 2 + 1] = sigm_(ov.y) * tanh_(cn1);
        }
        float4* dst = (float4*)(h_s + (u0 + ui) * 132 + e0);
        dst[0] = make_float4(hv[0], hv[1], hv[2], hv[3]);
        dst[1] = make_float4(hv[4], hv[5], hv[6], hv[7]);
    }
}

__global__ void __launch_bounds__(512, 1)
seq2seq_main(const float* __restrict__ X, const float* __restrict__ biasB,
             float* __restrict__ out)
{
    extern __shared__ float sm[];
    float* xs   = sm + XS_OFF;      // two buffers of 2112 floats
    float* h0_s = sm + H0_OFF;
    float* h1_s = sm + H1_OFF;
    float* y1_s = sm + Y1_OFF;
    float* c_s  = sm + CS_OFF;
    const float* gb = g_wbuf;

    const int tid = threadIdx.x;
    const int gg  = tid >> 4;     // 0..31
    const int eg  = tid & 15;     // 0..15
    const int g0  = gg * 8;
    const int e0  = eg * 8;
    const int u0  = gg * 2;
    const int b0  = blockIdx.x * 128;

    float* c0base = c_s;              // layer 0: slots 0..15
    float* c1base = c_s + 16 * 512;   // layer 1: slots 16..31

    // zero h0, h1, c
    for (int i = H0_OFF + tid; i < H1_OFF + 8448; i += 512) sm[i] = 0.f;
    for (int i = CS_OFF + tid; i < SMEM_FLOATS; i += 512) sm[i] = 0.f;

    // x staging mapping + preload x(0) into buffer 0
    const int xe = tid >> 2;            // elem 0..127
    const int xf = (tid & 3) * 4;       // feature 0,4,8,12
    const float* xbase = X + (size_t)(b0 + xe) * (TQ * FQ) + xf;
    {
        float4 v = *(const float4*)(xbase);
        xs[(xf + 0) * 132 + xe] = v.x;
        xs[(xf + 1) * 132 + xe] = v.y;
        xs[(xf + 2) * 132 + xe] = v.z;
        xs[(xf + 3) * 132 + xe] = v.w;
    }
    __syncthreads();

    ULL acc[32];

    // ================= encoder (3 barriers/step) =================
    for (int t = 0; t < TQ; t++) {
        // issue LDG for x(t+1) early (clamped; latency hidden under gemm0)
        int tn = (t + 1 < TQ) ? t + 1 : TQ - 1;
        float4 xv = *(const float4*)(xbase + tn * FQ);

        init_acc(acc, gb + OFF_BE0, g0);
        gemm_acc<16>(acc, gb + OFF_EIH0, xs + (t & 1) * 2112, g0, e0);
        gemm_acc<64>(acc, gb + OFF_EHH0, h0_s, g0, e0);
        __syncthreads();                            // S2: gemm0 reads done
        lstm_act(acc, c0base, h0_s, u0, e0, tid);   // writes h0
        {   // stage x(t+1) into the other buffer (its old readers long done)
            float* xb = xs + ((t + 1) & 1) * 2112;
            xb[(xf + 0) * 132 + xe] = xv.x;
            xb[(xf + 1) * 132 + xe] = xv.y;
            xb[(xf + 2) * 132 + xe] = xv.z;
            xb[(xf + 3) * 132 + xe] = xv.w;
        }
        __syncthreads();                            // S3: h0 + x(t+1) visible
        init_acc(acc, gb + OFF_BE1, g0);
        gemm_acc<64>(acc, gb + OFF_EIH1, h0_s, g0, e0);
        gemm_acc<64>(acc, gb + OFF_EHH1, h1_s, g0, e0);
        __syncthreads();                            // S4: gemm1 reads done
        lstm_act(acc, c1base, h1_s, u0, e0, tid);   // writes h1
        // next-iter S2 orders h1 writes before gemm1(t+1); gemm0(t+1) doesn't read h1
    }
    __syncthreads();    // encoder-final h0/h1 visible to decoder

    // ================= decoder (5 barriers/step) =================
    // carry: dh0 = enc h0 (h0_s), dh1 = enc h1 (h1_s); c := 0 (thread-owned slots)
#pragma unroll
    for (int j = 0; j < 16; j++) {
        c0base[j * 512 + tid] = 0.f;
        c1base[j * 512 + tid] = 0.f;
    }

    // head gemm2 mapping + per-batch bias preload
    const int o2  = tid & 15;
    const int e0b = (tid >> 4) * 4;
    float bb[4];
#pragma unroll
    for (int j = 0; j < 4; j++)
        bb[j] = biasB[(size_t)(b0 + e0b + j) * OUTQ + o2];
    const float b2v = gb[OFF_B2 + o2];

    for (int s = 0; s < HORQ; s++) {
        init_acc(acc, gb + OFF_BD0, g0);
        gemm_acc<64>(acc, gb + OFF_DIH0, h1_s, g0, e0);
        gemm_acc<64>(acc, gb + OFF_DHH0, h0_s, g0, e0);
        __syncthreads();                            // S2d
        lstm_act(acc, c0base, h0_s, u0, e0, tid);   // h0 := new dh0
        __syncthreads();                            // S3d
        init_acc(acc, gb + OFF_BD1, g0);
        gemm_acc<64>(acc, gb + OFF_DIH1, h0_s, g0, e0);
        gemm_acc<64>(acc, gb + OFF_DHH1, h1_s, g0, e0);
        __syncthreads();                            // S4d
        lstm_act(acc, c1base, h1_s, u0, e0, tid);   // h1 := new dh1
        __syncthreads();                            // S5d

        // head gemm1: y1 = relu(dh1 @ W1^T + b1); thread = 2 units x 4 elem-pairs
        {
            ULL a2[8];
            ULL bp0 = splat2(gb[OFF_B1 + u0]);
            ULL bp1 = splat2(gb[OFF_B1 + u0 + 1]);
#pragma unroll
            for (int ep = 0; ep < 4; ep++) { a2[ep] = bp0; a2[4 + ep] = bp1; }
            const ulonglong2* wp = (const ulonglong2*)(gb + OFF_W1D) + gg; // row stride 32
            const ulonglong2* hp = (const ulonglong2*)(h1_s + e0);         // row stride 33
#pragma unroll 4
            for (int k = 0; k < 64; k++) {
                ulonglong2 w = wp[k * 32];           // (u0 dup, u0+1 dup)
                ulonglong2 hA = hp[k * HROW_U2];
                ulonglong2 hB = hp[k * HROW_U2 + 1];
                ffma2(a2[0], w.x, hA.x);
                ffma2(a2[1], w.x, hA.y);
                ffma2(a2[2], w.x, hB.x);
                ffma2(a2[3], w.x, hB.y);
                ffma2(a2[4], w.y, hA.x);
                ffma2(a2[5], w.y, hA.y);
                ffma2(a2[6], w.y, hB.x);
                ffma2(a2[7], w.y, hB.y);
            }
            float r0[8], r1[8];
#pragma unroll
            for (int ep = 0; ep < 4; ep++) {
                float2 v0 = unpack2(a2[ep]);
                float2 v1 = unpack2(a2[4 + ep]);
                r0[ep * 2 + 0] = fmaxf(v0.x, 0.f);
                r0[ep * 2 + 1] = fmaxf(v0.y, 0.f);
                r1[ep * 2 + 0] = fmaxf(v1.x, 0.f);
                r1[ep * 2 + 1] = fmaxf(v1.y, 0.f);
            }
            float4* d0 = (float4*)(y1_s + (u0 + 0) * 132 + e0);
            float4* d1 = (float4*)(y1_s + (u0 + 1) * 132 + e0);
            d0[0] = make_float4(r0[0], r0[1], r0[2], r0[3]);
            d0[1] = make_float4(r0[4], r0[5], r0[6], r0[7]);
            d1[0] = make_float4(r1[0], r1[1], r1[2], r1[3]);
            d1[1] = make_float4(r1[4], r1[5], r1[6], r1[7]);
        }
        __syncthreads();                            // S6d: y1 visible

        // head gemm2: y = y1 @ W2^T + b2 + last_bias
        {
            float a3[4] = { b2v, b2v, b2v, b2v };
            const float* wp2 = gb + OFF_W2T + o2;  // row stride 16
            const float* yp  = y1_s + e0b;
#pragma unroll 4
            for (int k = 0; k < 64; k++) {
                float w = wp2[k * 16];
                float4 yv = *(const float4*)(yp + k * 132);
                a3[0] = fmaf(w, yv.x, a3[0]);
                a3[1] = fmaf(w, yv.y, a3[1]);
                a3[2] = fmaf(w, yv.z, a3[2]);
                a3[3] = fmaf(w, yv.w, a3[3]);
            }
#pragma unroll
            for (int j = 0; j < 4; j++)
                out[(size_t)(b0 + e0b + j) * (HORQ * OUTQ) + s * OUTQ + o2] = a3[j] + bb[j];
        }
        // no end barrier: next-step S2d..S5d separate all conflicting accesses
    }
}

// ---------------- launch ----------------
extern "C" void kernel_launch(void* const* d_in, const int* in_sizes, int n_in,
                              void* d_out, int out_size)
{
    (void)in_sizes; (void)n_in; (void)out_size;
    const float* X    = (const float*)d_in[0];
    const float* bias = (const float*)d_in[1];
    // d_in[2] = X_mask (all true, unused by reference)
    const float* eih0 = (const float*)d_in[3];
    const float* ehh0 = (const float*)d_in[4];
    const float* eb0  = (const float*)d_in[5];
    const float* eih1 = (const float*)d_in[6];
    const float* ehh1 = (const float*)d_in[7];
    const float* eb1  = (const float*)d_in[8];
    const float* dih0 = (const float*)d_in[9];
    const float* dhh0 = (const float*)d_in[10];
    const float* db0  = (const float*)d_in[11];
    const float* dih1 = (const float*)d_in[12];
    const float* dhh1 = (const float*)d_in[13];
    const float* db1  = (const float*)d_in[14];
    const float* rW1  = (const float*)d_in[15];
    const float* rb1  = (const float*)d_in[16];
    const float* rW2  = (const float*)d_in[17];
    const float* rb2  = (const float*)d_in[18];
    float* out = (float*)d_out;

    prep_all<<<dim3(128, 8), 256>>>(eih0, ehh0, eb0, eih1, ehh1, eb1,
                                    dih0, dhh0, db0, dih1, dhh1, db1,
                                    rW1, rb1, rW2, rb2);

    cudaFuncSetAttribute(seq2seq_main,
                         cudaFuncAttributeMaxDynamicSharedMemorySize, SMEM_BYTES);
    seq2seq_main<<<128, 512, SMEM_BYTES>>>(X, bias, out);
}

// round 16
// speedup vs baseline: 1.5850x; 1.5776x over previous
#include <cuda_runtime.h>

typedef unsigned long long ULL;

// ---------------- problem sizes ----------------
#define BQ   16384
#define TQ   96
#define FQ   16
#define HQ   64
#define HORQ 24
#define OUTQ 16

// ---------------- global weight scratch layout (floats, NON-duplicated) ----------------
#define OFF_EIH0 0          // 16*256
#define OFF_EHH0 4096       // 64*256
#define OFF_EIH1 20480
#define OFF_EHH1 36864
#define OFF_DIH0 53248
#define OFF_DHH0 69632
#define OFF_DIH1 86016
#define OFF_DHH1 102400
#define OFF_W1T  118784     // 64*64
#define OFF_W2T  122880     // 64*16
#define OFF_BE0  123904     // 256 each
#define OFF_BE1  124160
#define OFF_BD0  124416
#define OFF_BD1  124672
#define OFF_B1   124928     // 64
#define OFF_B2   124992     // 16
#define WBUF_TOTAL 125008

__device__ __align__(16) float g_wbuf[WBUF_TOTAL];

// ---------------- shared memory layout (floats) ----------------
// x (16x132) | h0 (64x132) | h1 (64x132) | y1 (64x132) | c ([2][512][17])
#define XS_OFF   0
#define H0_OFF   (16*132)
#define H1_OFF   (H0_OFF + 64*132)
#define Y1_OFF   (H1_OFF + 64*132)
#define CS_OFF   (Y1_OFF + 64*132)
#define SMEM_FLOATS (CS_OFF + 2*512*17)
#define SMEM_BYTES  (SMEM_FLOATS * 4)

// ---------------- f32x2 helpers ----------------
__device__ __forceinline__ ULL pack2(float lo, float hi) {
    ULL r;
    asm("mov.b64 %0, {%1, %2};" : "=l"(r) : "f"(lo), "f"(hi));
    return r;
}
__device__ __forceinline__ float2 unpack2(ULL v) {
    float2 r;
    asm("mov.b64 {%0, %1}, %2;" : "=f"(r.x), "=f"(r.y) : "l"(v));
    return r;
}
__device__ __forceinline__ ULL splat2(float x) { return pack2(x, x); }
__device__ __forceinline__ void ffma2(ULL& d, ULL a, ULL b) {
    asm("fma.rn.f32x2 %0, %1, %2, %0;" : "+l"(d) : "l"(a), "l"(b));
}

// fast activations (MUFU-based) — proven 2.9e-8 end-to-end
__device__ __forceinline__ float sigm_(float x) {
    return __fdividef(1.f, 1.f + __expf(-x));
}
__device__ __forceinline__ float tanh_(float x) {
    return __fdividef(2.f, 1.f + __expf(-2.f * x)) - 1.f;
}

// ---------------- single merged prep kernel ----------------
// grid (64, 8) x 256. m = blockIdx.y:
// m 0..6: seven 64x256 LSTM matrices (transpose + gate permute, non-dup).
// m == 7: EIH0 (16x256), W1T, W2T, 4 LSTM biases, b1, b2.
__global__ void prep_all(const float* __restrict__ eih0, const float* __restrict__ ehh0,
                         const float* __restrict__ eb0,
                         const float* __restrict__ eih1, const float* __restrict__ ehh1,
                         const float* __restrict__ eb1,
                         const float* __restrict__ dih0, const float* __restrict__ dhh0,
                         const float* __restrict__ db0,
                         const float* __restrict__ dih1, const float* __restrict__ dhh1,
                         const float* __restrict__ db1,
                         const float* __restrict__ W1, const float* __restrict__ b1,
                         const float* __restrict__ W2, const float* __restrict__ b2)
{
    int m = blockIdx.y;
    int i = blockIdx.x * 256 + threadIdx.x;   // 0..16383

    if (m < 7) {
        const float* src;
        int off;
        switch (m) {
            case 0: src = ehh0; off = OFF_EHH0; break;
            case 1: src = eih1; off = OFF_EIH1; break;
            case 2: src = ehh1; off = OFF_EHH1; break;
            case 3: src = dih0; off = OFF_DIH0; break;
            case 4: src = dhh0; off = OFF_DHH0; break;
            case 5: src = dih1; off = OFF_DIH1; break;
            default: src = dhh1; off = OFF_DHH1; break;
        }
        int k = i >> 8, p = i & 255;
        int u = p >> 2, tt = p & 3;
        g_wbuf[off + i] = src[(tt * 64 + u) * 64 + k];
        return;
    }

    if (i < 4096) {                              // EIH0, K=16
        int k = i >> 8, p = i & 255;
        int u = p >> 2, tt = p & 3;
        g_wbuf[OFF_EIH0 + i] = eih0[(tt * 64 + u) * 16 + k];
    } else if (i < 8192) {                       // W1T
        int j = i - 4096;
        int r = j >> 6, k = j & 63;
        g_wbuf[OFF_W1T + k * 64 + r] = W1[j];
    } else if (i < 9216) {                       // W2T
        int j = i - 8192;
        int o = j >> 6, k = j & 63;
        g_wbuf[OFF_W2T + k * 16 + o] = W2[j];
    } else if (i < 10240) {                      // 4 LSTM biases, permuted
        int j = i - 9216;
        int which = j >> 8;
        int p = j & 255;
        int u = p >> 2, tt = p & 3;
        const float* src = (which == 0) ? eb0 : (which == 1) ? eb1
                         : (which == 2) ? db0 : db1;
        int off = (which == 0) ? OFF_BE0 : (which == 1) ? OFF_BE1
                : (which == 2) ? OFF_BD0 : OFF_BD1;
        g_wbuf[off + p] = src[tt * 64 + u];
    } else if (i < 10304) {
        g_wbuf[OFF_B1 + (i - 10240)] = b1[i - 10240];
    } else if (i < 10320) {
        g_wbuf[OFF_B2 + (i - 10304)] = b2[i - 10304];
    }
}

// ---------------- main fused kernel ----------------
// 512 threads: gg = tid&31 -> gates g0=gg*8 (units u0=gg*2, u0+1),
//              eg = tid>>5 -> elems e0=eg*8.
// acc[gp*8+e]: gp = gate-pair 0..3 (permuted gates g0+2gp, g0+2gp+1), e = 0..7.

__device__ __forceinline__ void init_acc(ULL* acc, const float* __restrict__ bseg, int g0)
{
#pragma unroll
    for (int gp = 0; gp < 4; gp++) {
        float2 bv = *(const float2*)(bseg + g0 + gp * 2);
        ULL bp = pack2(bv.x, bv.y);
#pragma unroll
        for (int e = 0; e < 8; e++) acc[gp * 8 + e] = bp;
    }
}

__device__ __forceinline__ void fma_block(ULL* acc, ULL w0, ULL w1, ULL w2, ULL w3,
                                          float4 hc, float4 hd)
{
    ULL hp8[8];
    hp8[0] = splat2(hc.x); hp8[1] = splat2(hc.y); hp8[2] = splat2(hc.z); hp8[3] = splat2(hc.w);
    hp8[4] = splat2(hd.x); hp8[5] = splat2(hd.y); hp8[6] = splat2(hd.z); hp8[7] = splat2(hd.w);
#pragma unroll
    for (int e = 0; e < 8; e++) ffma2(acc[0 * 8 + e], w0, hp8[e]);
#pragma unroll
    for (int e = 0; e < 8; e++) ffma2(acc[1 * 8 + e], w1, hp8[e]);
#pragma unroll
    for (int e = 0; e < 8; e++) ffma2(acc[2 * 8 + e], w2, hp8[e]);
#pragma unroll
    for (int e = 0; e < 8; e++) ffma2(acc[3 * 8 + e], w3, hp8[e]);
}

// Depth-2 double-buffered weight prefetch; h (SMEM, 29cyc) at depth-1.
// K must be even and >= 2.
template <int K>
__device__ __forceinline__ void gemm_acc(ULL* acc, const float* __restrict__ Wt,
                                         const float* __restrict__ src, int g0, int e0)
{
    const float* wpa = Wt + g0;          // rows k   (even)
    const float* wpb = wpa + 256;        // rows k+1 (odd)
    ulonglong2 wa0 = *(const ulonglong2*)(wpa);
    ulonglong2 wa1 = *(const ulonglong2*)(wpa + 4);
    ulonglong2 wb0 = *(const ulonglong2*)(wpb);
    ulonglong2 wb1 = *(const ulonglong2*)(wpb + 4);
    wpa += 512; wpb += 512;
    const float* hptr = src + e0;
    float4 ha = *(const float4*)(hptr);
    float4 hb = *(const float4*)(hptr + 4);
    hptr += 132;
#pragma unroll 2
    for (int k = 0; k < K; k += 2) {
        bool more = (k + 2 < K);
        // ---- even sub-iter: consume wa + h(k); prefetch w(k+2), h(k+1) ----
        {
            ULL w0 = wa0.x, w1 = wa0.y, w2 = wa1.x, w3 = wa1.y;
            float4 hc = ha, hd = hb;
            if (more) {
                wa0 = *(const ulonglong2*)(wpa);
                wa1 = *(const ulonglong2*)(wpa + 4);
                wpa += 512;
            }
            ha = *(const float4*)(hptr);       // h(k+1), always in-bounds
            hb = *(const float4*)(hptr + 4);
            hptr += 132;
            fma_block(acc, w0, w1, w2, w3, hc, hd);
        }
        // ---- odd sub-iter: consume wb + h(k+1); prefetch w(k+3), h(k+2) ----
        {
            ULL w0 = wb0.x, w1 = wb0.y, w2 = wb1.x, w3 = wb1.y;
            float4 hc = ha, hd = hb;
            if (more) {
                wb0 = *(const ulonglong2*)(wpb);
                wb1 = *(const ulonglong2*)(wpb + 4);
                wpb += 512;
                ha = *(const float4*)(hptr);   // h(k+2)
                hb = *(const float4*)(hptr + 4);
                hptr += 132;
            }
            fma_block(acc, w0, w1, w2, w3, hc, hd);
        }
    }
}

// gate activation + state update; writes new h into h_s, updates c in SMEM cbuf
__device__ __forceinline__ void lstm_act(const ULL* acc, float* cbuf,
                                         float* __restrict__ h_s, int u0, int e0)
{
#pragma unroll
    for (int ui = 0; ui < 2; ui++) {
        float hv[8];
#pragma unroll
        for (int e = 0; e < 8; e++) {
            float2 if_ = unpack2(acc[(ui * 2 + 0) * 8 + e]);   // (i, f)
            float2 go_ = unpack2(acc[(ui * 2 + 1) * 8 + e]);   // (g, o)
            float cold = cbuf[ui * 8 + e];
            float cn = sigm_(if_.y) * cold + sigm_(if_.x) * tanh_(go_.x);
            cbuf[ui * 8 + e] = cn;
            hv[e] = sigm_(go_.y) * tanh_(cn);
        }
        float4* dst = (float4*)(h_s + (u0 + ui) * 132 + e0);
        dst[0] = make_float4(hv[0], hv[1], hv[2], hv[3]);
        dst[1] = make_float4(hv[4], hv[5], hv[6], hv[7]);
    }
}

__global__ void __launch_bounds__(512, 1)
seq2seq_main(const float* __restrict__ X, const float* __restrict__ biasB,
             float* __restrict__ out)
{
    extern __shared__ float sm[];
    float* x_s  = sm + XS_OFF;
    float* h0_s = sm + H0_OFF;
    float* h1_s = sm + H1_OFF;
    float* y1_s = sm + Y1_OFF;
    float* c_s  = sm + CS_OFF;
    const float* gb = g_wbuf;

    const int tid = threadIdx.x;
    const int gg  = tid & 31;
    const int eg  = tid >> 5;
    const int g0  = gg * 8;
    const int e0  = eg * 8;
    const int u0  = gg * 2;
    const int b0  = blockIdx.x * 128;

    float* c0buf = c_s + tid * 17;
    float* c1buf = c_s + 512 * 17 + tid * 17;

    // zero all state
    for (int i = tid; i < SMEM_FLOATS; i += 512) sm[i] = 0.f;
    __syncthreads();

    ULL acc[32];

    // ================= encoder =================
    for (int t = 0; t < TQ; t++) {
        // stage x_t tile: x_s[f][e]
        {
            int e = tid >> 2, f = (tid & 3) * 4;
            float4 v = *(const float4*)(X + (size_t)(b0 + e) * (TQ * FQ) + t * FQ + f);
            x_s[(f + 0) * 132 + e] = v.x;
            x_s[(f + 1) * 132 + e] = v.y;
            x_s[(f + 2) * 132 + e] = v.z;
            x_s[(f + 3) * 132 + e] = v.w;
        }
        __syncthreads();
        // layer 0: z = b + x@Wih0^T + h0@Whh0^T
        init_acc(acc, gb + OFF_BE0, g0);
        gemm_acc<16>(acc, gb + OFF_EIH0, x_s, g0, e0);
        gemm_acc<64>(acc, gb + OFF_EHH0, h0_s, g0, e0);
        __syncthreads();
        lstm_act(acc, c0buf, h0_s, u0, e0);
        __syncthreads();
        // layer 1: z = b + h0@Wih1^T + h1@Whh1^T
        init_acc(acc, gb + OFF_BE1, g0);
        gemm_acc<64>(acc, gb + OFF_EIH1, h0_s, g0, e0);
        gemm_acc<64>(acc, gb + OFF_EHH1, h1_s, g0, e0);
        __syncthreads();
        lstm_act(acc, c1buf, h1_s, u0, e0);
        __syncthreads();
    }

    // ================= decoder =================
    // carry: dh0 = enc h0 (h0_s), dh1 = enc h1 (h1_s) -- in place; c := 0
#pragma unroll
    for (int j = 0; j < 16; j++) { c0buf[j] = 0.f; c1buf[j] = 0.f; }

    // head gemm2 mapping + per-batch bias preload
    const int o2  = tid & 15;
    const int e0b = (tid >> 4) * 4;
    float bb[4];
#pragma unroll
    for (int j = 0; j < 4; j++)
        bb[j] = biasB[(size_t)(b0 + e0b + j) * OUTQ + o2];
    const float b2v = gb[OFF_B2 + o2];

    for (int s = 0; s < HORQ; s++) {
        // dec layer 0: input = dh1 (h1_s), hidden = dh0 (h0_s)
        init_acc(acc, gb + OFF_BD0, g0);
        gemm_acc<64>(acc, gb + OFF_DIH0, h1_s, g0, e0);
        gemm_acc<64>(acc, gb + OFF_DHH0, h0_s, g0, e0);
        __syncthreads();
        lstm_act(acc, c0buf, h0_s, u0, e0);     // h0_s := new dh0
        __syncthreads();
        // dec layer 1: input = new dh0, hidden = dh1
        init_acc(acc, gb + OFF_BD1, g0);
        gemm_acc<64>(acc, gb + OFF_DIH1, h0_s, g0, e0);
        gemm_acc<64>(acc, gb + OFF_DHH1, h1_s, g0, e0);
        __syncthreads();
        lstm_act(acc, c1buf, h1_s, u0, e0);     // h1_s := new dh1
        __syncthreads();

        // head gemm1: y1 = relu(dh1 @ W1^T + b1), rows u0,u0+1 per thread
        {
            ULL a2[8];
            float2 bv = *(const float2*)(gb + OFF_B1 + u0);
            ULL bp = pack2(bv.x, bv.y);
#pragma unroll
            for (int e = 0; e < 8; e++) a2[e] = bp;
            const float* wp = gb + OFF_W1T + u0;   // row stride 64
            const float* hp = h1_s + e0;
#pragma unroll 4
            for (int k = 0; k < 64; k++) {
                ULL w = *(const ULL*)(wp); wp += 64;
                float4 hA = *(const float4*)(hp);
                float4 hB = *(const float4*)(hp + 4);
                hp += 132;
                ffma2(a2[0], w, splat2(hA.x));
                ffma2(a2[1], w, splat2(hA.y));
                ffma2(a2[2], w, splat2(hA.z));
                ffma2(a2[3], w, splat2(hA.w));
                ffma2(a2[4], w, splat2(hB.x));
                ffma2(a2[5], w, splat2(hB.y));
                ffma2(a2[6], w, splat2(hB.z));
                ffma2(a2[7], w, splat2(hB.w));
            }
#pragma unroll
            for (int e = 0; e < 8; e++) {
                float2 v = unpack2(a2[e]);
                y1_s[(u0 + 0) * 132 + e0 + e] = fmaxf(v.x, 0.f);
                y1_s[(u0 + 1) * 132 + e0 + e] = fmaxf(v.y, 0.f);
            }
        }
        __syncthreads();

        // head gemm2: y = y1 @ W2^T + b2 + last_bias; out[b][s][o]
        {
            float a3[4] = { b2v, b2v, b2v, b2v };
            const float* wp2 = gb + OFF_W2T + o2;  // row stride 16
            const float* yp  = y1_s + e0b;
#pragma unroll 4
            for (int k = 0; k < 64; k++) {
                float w = wp2[k * 16];
                float4 yv = *(const float4*)(yp + k * 132);
                a3[0] = fmaf(w, yv.x, a3[0]);
                a3[1] = fmaf(w, yv.y, a3[1]);
                a3[2] = fmaf(w, yv.z, a3[2]);
                a3[3] = fmaf(w, yv.w, a3[3]);
            }
#pragma unroll
            for (int j = 0; j < 4; j++)
                out[(size_t)(b0 + e0b + j) * (HORQ * OUTQ) + s * OUTQ + o2] = a3[j] + bb[j];
        }
        __syncthreads();
    }
}

// ---------------- launch ----------------
extern "C" void kernel_launch(void* const* d_in, const int* in_sizes, int n_in,
                              void* d_out, int out_size)
{
    (void)in_sizes; (void)n_in; (void)out_size;
    const float* X    = (const float*)d_in[0];
    const float* bias = (const float*)d_in[1];
    // d_in[2] = X_mask (all true, unused by reference)
    const float* eih0 = (const float*)d_in[3];
    const float* ehh0 = (const float*)d_in[4];
    const float* eb0  = (const float*)d_in[5];
    const float* eih1 = (const float*)d_in[6];
    const float* ehh1 = (const float*)d_in[7];
    const float* eb1  = (const float*)d_in[8];
    const float* dih0 = (const float*)d_in[9];
    const float* dhh0 = (const float*)d_in[10];
    const float* db0  = (const float*)d_in[11];
    const float* dih1 = (const float*)d_in[12];
    const float* dhh1 = (const float*)d_in[13];
    const float* db1  = (const float*)d_in[14];
    const float* rW1  = (const float*)d_in[15];
    const float* rb1  = (const float*)d_in[16];
    const float* rW2  = (const float*)d_in[17];
    const float* rb2  = (const float*)d_in[18];
    float* out = (float*)d_out;

    prep_all<<<dim3(64, 8), 256>>>(eih0, ehh0, eb0, eih1, ehh1, eb1,
                                   dih0, dhh0, db0, dih1, dhh1, db1,
                                   rW1, rb1, rW2, rb2);

    cudaFuncSetAttribute(seq2seq_main,
                         cudaFuncAttributeMaxDynamicSharedMemorySize, SMEM_BYTES);
    seq2seq_main<<<128, 512, SMEM_BYTES>>>(X, bias, out);
}

// round 17
// speedup vs baseline: 2.0743x; 1.3087x over previous
#include <cuda_runtime.h>

typedef unsigned long long ULL;

// ---------------- problem sizes ----------------
#define BQ   16384
#define TQ   96
#define FQ   16
#define HQ   64
#define HORQ 24
#define OUTQ 16

// batch tile per CTA
#define ETILE 64

// ---------------- global weight scratch layout (floats, NON-duplicated) ----------------
#define OFF_EIH0 0          // 16*256
#define OFF_EHH0 4096       // 64*256
#define OFF_EIH1 20480
#define OFF_EHH1 36864
#define OFF_DIH0 53248
#define OFF_DHH0 69632
#define OFF_DIH1 86016
#define OFF_DHH1 102400
#define OFF_W1T  118784     // 64*64
#define OFF_W2T  122880     // 64*16
#define OFF_BE0  123904     // 256 each
#define OFF_BE1  124160
#define OFF_BD0  124416
#define OFF_BD1  124672
#define OFF_B1   124928     // 64
#define OFF_B2   124992     // 16
#define WBUF_TOTAL 125008

__device__ __align__(16) float g_wbuf[WBUF_TOTAL];

// ---------------- shared memory layout (floats) ----------------
// row stride 68 floats (= 272 B = 17 x 16 B, float4-aligned, modest banking)
// x (16x68) | h0 (64x68) | h1 (64x68) | y1 (64x68) | c ([2][256][17])
#define RSTR     68
#define XS_OFF   0
#define H0_OFF   (16*RSTR)
#define H1_OFF   (H0_OFF + 64*RSTR)
#define Y1_OFF   (H1_OFF + 64*RSTR)
#define CS_OFF   (Y1_OFF + 64*RSTR)
#define SMEM_FLOATS (CS_OFF + 2*256*17)
#define SMEM_BYTES  (SMEM_FLOATS * 4)

// ---------------- f32x2 helpers ----------------
__device__ __forceinline__ ULL pack2(float lo, float hi) {
    ULL r;
    asm("mov.b64 %0, {%1, %2};" : "=l"(r) : "f"(lo), "f"(hi));
    return r;
}
__device__ __forceinline__ float2 unpack2(ULL v) {
    float2 r;
    asm("mov.b64 {%0, %1}, %2;" : "=f"(r.x), "=f"(r.y) : "l"(v));
    return r;
}
__device__ __forceinline__ ULL splat2(float x) { return pack2(x, x); }
__device__ __forceinline__ void ffma2(ULL& d, ULL a, ULL b) {
    asm("fma.rn.f32x2 %0, %1, %2, %0;" : "+l"(d) : "l"(a), "l"(b));
}

// fast activations (MUFU-based) — proven 2.9e-8 end-to-end
__device__ __forceinline__ float sigm_(float x) {
    return __fdividef(1.f, 1.f + __expf(-x));
}
__device__ __forceinline__ float tanh_(float x) {
    return __fdividef(2.f, 1.f + __expf(-2.f * x)) - 1.f;
}

// ---------------- single merged prep kernel ----------------
// grid (64, 8) x 256. m = blockIdx.y:
// m 0..6: seven 64x256 LSTM matrices (transpose + gate permute, non-dup).
// m == 7: EIH0 (16x256), W1T, W2T, 4 LSTM biases, b1, b2.
__global__ void prep_all(const float* __restrict__ eih0, const float* __restrict__ ehh0,
                         const float* __restrict__ eb0,
                         const float* __restrict__ eih1, const float* __restrict__ ehh1,
                         const float* __restrict__ eb1,
                         const float* __restrict__ dih0, const float* __restrict__ dhh0,
                         const float* __restrict__ db0,
                         const float* __restrict__ dih1, const float* __restrict__ dhh1,
                         const float* __restrict__ db1,
                         const float* __restrict__ W1, const float* __restrict__ b1,
                         const float* __restrict__ W2, const float* __restrict__ b2)
{
    int m = blockIdx.y;
    int i = blockIdx.x * 256 + threadIdx.x;   // 0..16383

    if (m < 7) {
        const float* src;
        int off;
        switch (m) {
            case 0: src = ehh0; off = OFF_EHH0; break;
            case 1: src = eih1; off = OFF_EIH1; break;
            case 2: src = ehh1; off = OFF_EHH1; break;
            case 3: src = dih0; off = OFF_DIH0; break;
            case 4: src = dhh0; off = OFF_DHH0; break;
            case 5: src = dih1; off = OFF_DIH1; break;
            default: src = dhh1; off = OFF_DHH1; break;
        }
        int k = i >> 8, p = i & 255;
        int u = p >> 2, tt = p & 3;
        g_wbuf[off + i] = src[(tt * 64 + u) * 64 + k];
        return;
    }

    if (i < 4096) {                              // EIH0, K=16
        int k = i >> 8, p = i & 255;
        int u = p >> 2, tt = p & 3;
        g_wbuf[OFF_EIH0 + i] = eih0[(tt * 64 + u) * 16 + k];
    } else if (i < 8192) {                       // W1T
        int j = i - 4096;
        int r = j >> 6, k = j & 63;
        g_wbuf[OFF_W1T + k * 64 + r] = W1[j];
    } else if (i < 9216) {                       // W2T
        int j = i - 8192;
        int o = j >> 6, k = j & 63;
        g_wbuf[OFF_W2T + k * 16 + o] = W2[j];
    } else if (i < 10240) {                      // 4 LSTM biases, permuted
        int j = i - 9216;
        int which = j >> 8;
        int p = j & 255;
        int u = p >> 2, tt = p & 3;
        const float* src = (which == 0) ? eb0 : (which == 1) ? eb1
                         : (which == 2) ? db0 : db1;
        int off = (which == 0) ? OFF_BE0 : (which == 1) ? OFF_BE1
                : (which == 2) ? OFF_BD0 : OFF_BD1;
        g_wbuf[off + p] = src[tt * 64 + u];
    } else if (i < 10304) {
        g_wbuf[OFF_B1 + (i - 10240)] = b1[i - 10240];
    } else if (i < 10320) {
        g_wbuf[OFF_B2 + (i - 10304)] = b2[i - 10304];
    }
}

// ---------------- main fused kernel ----------------
// 256 threads, 2 CTAs/SM: gg = tid&31 -> gates g0=gg*8 (units u0=gg*2, u0+1),
//                         eg = tid>>5 (0..7) -> elems e0=eg*8 (of 64).
// Warp = all 32 gg values x one eg: weight LDG spans full row, h LDS broadcast.
// acc[gp*8+e]: gp = gate-pair 0..3 (permuted gates g0+2gp, g0+2gp+1), e = 0..7.

__device__ __forceinline__ void init_acc(ULL* acc, const float* __restrict__ bseg, int g0)
{
#pragma unroll
    for (int gp = 0; gp < 4; gp++) {
        float2 bv = *(const float2*)(bseg + g0 + gp * 2);
        ULL bp = pack2(bv.x, bv.y);
#pragma unroll
        for (int e = 0; e < 8; e++) acc[gp * 8 + e] = bp;
    }
}

// distance-1 prefetch (the proven 5671 version), h row stride RSTR
template <int K>
__device__ __forceinline__ void gemm_acc(ULL* acc, const float* __restrict__ Wt,
                                         const float* __restrict__ src, int g0, int e0)
{
    const float* wptr = Wt + g0;        // row stride 256 (global, L2/L1-resident)
    const float* hptr = src + e0;       // row stride RSTR (SMEM)
    ulonglong2 w0 = *(const ulonglong2*)(wptr);
    ulonglong2 w1 = *(const ulonglong2*)(wptr + 4);
    float4 ha = *(const float4*)(hptr);
    float4 hb = *(const float4*)(hptr + 4);
#pragma unroll 2
    for (int k = 0; k < K; k++) {
        ULL w[4];
        w[0] = w0.x; w[1] = w0.y; w[2] = w1.x; w[3] = w1.y;
        float4 hc = ha, hd = hb;
        if (k + 1 < K) {                // prefetch next k
            wptr += 256; hptr += RSTR;
            w0 = *(const ulonglong2*)(wptr);
            w1 = *(const ulonglong2*)(wptr + 4);
            ha = *(const float4*)(hptr);
            hb = *(const float4*)(hptr + 4);
        }
        ULL hp[8];
        hp[0] = splat2(hc.x); hp[1] = splat2(hc.y); hp[2] = splat2(hc.z); hp[3] = splat2(hc.w);
        hp[4] = splat2(hd.x); hp[5] = splat2(hd.y); hp[6] = splat2(hd.z); hp[7] = splat2(hd.w);
#pragma unroll
        for (int gp = 0; gp < 4; gp++)
#pragma unroll
            for (int e = 0; e < 8; e++)
                ffma2(acc[gp * 8 + e], w[gp], hp[e]);
    }
}

// gate activation + state update; writes new h into h_s, updates c in SMEM cbuf
__device__ __forceinline__ void lstm_act(const ULL* acc, float* cbuf,
                                         float* __restrict__ h_s, int u0, int e0)
{
#pragma unroll
    for (int ui = 0; ui < 2; ui++) {
        float hv[8];
#pragma unroll
        for (int e = 0; e < 8; e++) {
            float2 if_ = unpack2(acc[(ui * 2 + 0) * 8 + e]);   // (i, f)
            float2 go_ = unpack2(acc[(ui * 2 + 1) * 8 + e]);   // (g, o)
            float cold = cbuf[ui * 8 + e];
            float cn = sigm_(if_.y) * cold + sigm_(if_.x) * tanh_(go_.x);
            cbuf[ui * 8 + e] = cn;
            hv[e] = sigm_(go_.y) * tanh_(cn);
        }
        float4* dst = (float4*)(h_s + (u0 + ui) * RSTR + e0);
        dst[0] = make_float4(hv[0], hv[1], hv[2], hv[3]);
        dst[1] = make_float4(hv[4], hv[5], hv[6], hv[7]);
    }
}

__global__ void __launch_bounds__(256, 2)
seq2seq_main(const float* __restrict__ X, const float* __restrict__ biasB,
             float* __restrict__ out)
{
    extern __shared__ float sm[];
    float* x_s  = sm + XS_OFF;
    float* h0_s = sm + H0_OFF;
    float* h1_s = sm + H1_OFF;
    float* y1_s = sm + Y1_OFF;
    float* c_s  = sm + CS_OFF;
    const float* gb = g_wbuf;

    const int tid = threadIdx.x;
    const int gg  = tid & 31;
    const int eg  = tid >> 5;     // 0..7
    const int g0  = gg * 8;
    const int e0  = eg * 8;
    const int u0  = gg * 2;
    const int b0  = blockIdx.x * ETILE;

    float* c0buf = c_s + tid * 17;
    float* c1buf = c_s + 256 * 17 + tid * 17;

    // zero all state
    for (int i = tid; i < SMEM_FLOATS; i += 256) sm[i] = 0.f;
    __syncthreads();

    ULL acc[32];

    // ================= encoder =================
    for (int t = 0; t < TQ; t++) {
        // stage x_t tile: x_s[f][e]  (64 elems x 16 f = 1024 floats = 256 x float4)
        {
            int e = tid >> 2, f = (tid & 3) * 4;
            float4 v = *(const float4*)(X + (size_t)(b0 + e) * (TQ * FQ) + t * FQ + f);
            x_s[(f + 0) * RSTR + e] = v.x;
            x_s[(f + 1) * RSTR + e] = v.y;
            x_s[(f + 2) * RSTR + e] = v.z;
            x_s[(f + 3) * RSTR + e] = v.w;
        }
        __syncthreads();
        // layer 0: z = b + x@Wih0^T + h0@Whh0^T
        init_acc(acc, gb + OFF_BE0, g0);
        gemm_acc<16>(acc, gb + OFF_EIH0, x_s, g0, e0);
        gemm_acc<64>(acc, gb + OFF_EHH0, h0_s, g0, e0);
        __syncthreads();
        lstm_act(acc, c0buf, h0_s, u0, e0);
        __syncthreads();
        // layer 1: z = b + h0@Wih1^T + h1@Whh1^T
        init_acc(acc, gb + OFF_BE1, g0);
        gemm_acc<64>(acc, gb + OFF_EIH1, h0_s, g0, e0);
        gemm_acc<64>(acc, gb + OFF_EHH1, h1_s, g0, e0);
        __syncthreads();
        lstm_act(acc, c1buf, h1_s, u0, e0);
        __syncthreads();
    }

    // ================= decoder =================
    // carry: dh0 = enc h0 (h0_s), dh1 = enc h1 (h1_s) -- in place; c := 0
#pragma unroll
    for (int j = 0; j < 16; j++) { c0buf[j] = 0.f; c1buf[j] = 0.f; }

    // head gemm2 mapping + per-batch bias preload
    const int o2  = tid & 15;
    const int e0b = (tid >> 4) * 4;    // 0..60
    float bb[4];
#pragma unroll
    for (int j = 0; j < 4; j++)
        bb[j] = biasB[(size_t)(b0 + e0b + j) * OUTQ + o2];
    const float b2v = gb[OFF_B2 + o2];

    for (int s = 0; s < HORQ; s++) {
        // dec layer 0: input = dh1 (h1_s), hidden = dh0 (h0_s)
        init_acc(acc, gb + OFF_BD0, g0);
        gemm_acc<64>(acc, gb + OFF_DIH0, h1_s, g0, e0);
        gemm_acc<64>(acc, gb + OFF_DHH0, h0_s, g0, e0);
        __syncthreads();
        lstm_act(acc, c0buf, h0_s, u0, e0);     // h0_s := new dh0
        __syncthreads();
        // dec layer 1: input = new dh0, hidden = dh1
        init_acc(acc, gb + OFF_BD1, g0);
        gemm_acc<64>(acc, gb + OFF_DIH1, h0_s, g0, e0);
        gemm_acc<64>(acc, gb + OFF_DHH1, h1_s, g0, e0);
        __syncthreads();
        lstm_act(acc, c1buf, h1_s, u0, e0);     // h1_s := new dh1
        __syncthreads();

        // head gemm1: y1 = relu(dh1 @ W1^T + b1), rows u0,u0+1 per thread
        {
            ULL a2[8];
            float2 bv = *(const float2*)(gb + OFF_B1 + u0);
            ULL bp = pack2(bv.x, bv.y);
#pragma unroll
            for (int e = 0; e < 8; e++) a2[e] = bp;
            const float* wp = gb + OFF_W1T + u0;   // row stride 64
            const float* hp = h1_s + e0;
#pragma unroll 4
            for (int k = 0; k < 64; k++) {
                ULL w = *(const ULL*)(wp); wp += 64;
                float4 hA = *(const float4*)(hp);
                float4 hB = *(const float4*)(hp + 4);
                hp += RSTR;
                ffma2(a2[0], w, splat2(hA.x));
                ffma2(a2[1], w, splat2(hA.y));
                ffma2(a2[2], w, splat2(hA.z));
                ffma2(a2[3], w, splat2(hA.w));
                ffma2(a2[4], w, splat2(hB.x));
                ffma2(a2[5], w, splat2(hB.y));
                ffma2(a2[6], w, splat2(hB.z));
                ffma2(a2[7], w, splat2(hB.w));
            }
#pragma unroll
            for (int e = 0; e < 8; e++) {
                float2 v = unpack2(a2[e]);
                y1_s[(u0 + 0) * RSTR + e0 + e] = fmaxf(v.x, 0.f);
                y1_s[(u0 + 1) * RSTR + e0 + e] = fmaxf(v.y, 0.f);
            }
        }
        __syncthreads();

        // head gemm2: y = y1 @ W2^T + b2 + last_bias; out[b][s][o]
        {
            float a3[4] = { b2v, b2v, b2v, b2v };
            const float* wp2 = gb + OFF_W2T + o2;  // row stride 16
            const float* yp  = y1_s + e0b;
#pragma unroll 4
            for (int k = 0; k < 64; k++) {
                float w = wp2[k * 16];
                float4 yv = *(const float4*)(yp + k * RSTR);
                a3[0] = fmaf(w, yv.x, a3[0]);
                a3[1] = fmaf(w, yv.y, a3[1]);
                a3[2] = fmaf(w, yv.z, a3[2]);
                a3[3] = fmaf(w, yv.w, a3[3]);
            }
#pragma unroll
            for (int j = 0; j < 4; j++)
                out[(size_t)(b0 + e0b + j) * (HORQ * OUTQ) + s * OUTQ + o2] = a3[j] + bb[j];
        }
        __syncthreads();
    }
}

// ---------------- launch ----------------
extern "C" void kernel_launch(void* const* d_in, const int* in_sizes, int n_in,
                              void* d_out, int out_size)
{
    (void)in_sizes; (void)n_in; (void)out_size;
    const float* X    = (const float*)d_in[0];
    const float* bias = (const float*)d_in[1];
    // d_in[2] = X_mask (all true, unused by reference)
    const float* eih0 = (const float*)d_in[3];
    const float* ehh0 = (const float*)d_in[4];
    const float* eb0  = (const float*)d_in[5];
    const float* eih1 = (const float*)d_in[6];
    const float* ehh1 = (const float*)d_in[7];
    const float* eb1  = (const float*)d_in[8];
    const float* dih0 = (const float*)d_in[9];
    const float* dhh0 = (const float*)d_in[10];
    const float* db0  = (const float*)d_in[11];
    const float* dih1 = (const float*)d_in[12];
    const float* dhh1 = (const float*)d_in[13];
    const float* db1  = (const float*)d_in[14];
    const float* rW1  = (const float*)d_in[15];
    const float* rb1  = (const float*)d_in[16];
    const float* rW2  = (const float*)d_in[17];
    const float* rb2  = (const float*)d_in[18];
    float* out = (float*)d_out;

    prep_all<<<dim3(64, 8), 256>>>(eih0, ehh0, eb0, eih1, ehh1, eb1,
                                   dih0, dhh0, db0, dih1, dhh1, db1,
                                   rW1, rb1, rW2, rb2);

    cudaFuncSetAttribute(seq2seq_main,
                         cudaFuncAttributeMaxDynamicSharedMemorySize, SMEM_BYTES);
    seq2seq_main<<<BQ / ETILE, 256, SMEM_BYTES>>>(X, bias, out);
}